// round 6
// baseline (speedup 1.0000x reference)
#include <cuda_runtime.h>
#include <cuda_bf16.h>
#include <cstdint>

#define NCTX 2048
#define DH   64
#define QM   64      // q rows per CTA
#define TN   64      // kv tokens per tile
#define NTH  128     // 4 warps
#define KROW 72      // smem row stride in bf16 elems (144B, 16B-aligned, ldmatrix conflict-free)

static __device__ __forceinline__ uint32_t smem_u32(const void* p) {
    uint32_t a;
    asm("{ .reg .u64 t; cvta.to.shared.u64 t, %1; cvt.u32.u64 %0, t; }" : "=r"(a) : "l"(p));
    return a;
}

// D += A * B, m16n8k16 bf16 -> fp32
#define MMA(d, a, b) \
    asm volatile("mma.sync.aligned.m16n8k16.row.col.f32.bf16.bf16.f32 " \
        "{%0,%1,%2,%3}, {%4,%5,%6,%7}, {%8,%9}, {%0,%1,%2,%3};" \
        : "+f"((d)[0]), "+f"((d)[1]), "+f"((d)[2]), "+f"((d)[3]) \
        : "r"((a)[0]), "r"((a)[1]), "r"((a)[2]), "r"((a)[3]), "r"((b)[0]), "r"((b)[1]))

#define LDSM4(r, addr) \
    asm volatile("ldmatrix.sync.aligned.m8n8.x4.shared.b16 {%0,%1,%2,%3}, [%4];" \
        : "=r"((r)[0]), "=r"((r)[1]), "=r"((r)[2]), "=r"((r)[3]) : "r"(addr))

#define LDSM4T(r, addr) \
    asm volatile("ldmatrix.sync.aligned.m8n8.x4.trans.shared.b16 {%0,%1,%2,%3}, [%4];" \
        : "=r"((r)[0]), "=r"((r)[1]), "=r"((r)[2]), "=r"((r)[3]) : "r"(addr))

// split (a,b) into packed bf16 hi pair + residual lo pair
static __device__ __forceinline__ void split_pair(float a, float b, uint32_t& h, uint32_t& l) {
    __nv_bfloat16 ha = __float2bfloat16(a);
    __nv_bfloat16 hb = __float2bfloat16(b);
    __nv_bfloat16 la = __float2bfloat16(a - __bfloat162float(ha));
    __nv_bfloat16 lb = __float2bfloat16(b - __bfloat162float(hb));
    h = ((uint32_t)__bfloat16_as_ushort(hb) << 16) | (uint32_t)__bfloat16_as_ushort(ha);
    l = ((uint32_t)__bfloat16_as_ushort(lb) << 16) | (uint32_t)__bfloat16_as_ushort(la);
}

__global__ __launch_bounds__(NTH, 3)
void bsattn_mma_kernel(const float* __restrict__ q, const float* __restrict__ k,
                       const float* __restrict__ v, const float* __restrict__ smp,
                       const int* __restrict__ rsv, const int* __restrict__ rev,
                       float* __restrict__ out)
{
    // Kh | Kl | Vh | Vl, each 64 tok x 72 bf16 (144B rows) = 36.9KB
    __shared__ __align__(16) uint16_t sm[4 * TN * KROW];
    __shared__ int red_lo, red_hi;

    uint16_t* sKh = sm;
    uint16_t* sKl = sm + 1 * TN * KROW;
    uint16_t* sVh = sm + 2 * TN * KROW;
    uint16_t* sVl = sm + 3 * TN * KROW;

    const int tid  = threadIdx.x;
    const int wid  = tid >> 5;
    const int lane = tid & 31;
    const int qb   = gridDim.x - 1 - blockIdx.x;   // heavy q-tiles first
    const int bh   = blockIdx.y;
    const int q0   = qb * QM;

    const float sc = *smp;
    const float* qp = q   + ((size_t)bh * NCTX + q0) * DH;
    const float* kp = k   + (size_t)bh * NCTX * DH;
    const float* vp = v   + (size_t)bh * NCTX * DH;
    float*       op = out + ((size_t)bh * NCTX + q0) * DH;

    // this thread's two query rows (within mma fragments)
    const int rloc = wid * 16 + (lane >> 2);       // row for c0/c1
    const int rg0  = q0 + rloc;
    const int rs0 = rsv[rg0],     re0 = rev[rg0];
    const int rs1 = rsv[rg0 + 8], re1 = rev[rg0 + 8];

    if (tid == 0) { red_lo = 0x7fffffff; red_hi = 0; }
    __syncthreads();
    atomicMin(&red_lo, min(rs0, rs1));
    atomicMax(&red_hi, max(re0, re1));

    // ---- Preload Q as split A-fragments (registers, reused every tile) ----
    uint32_t qh[4][4], ql[4][4];
#pragma unroll
    for (int s = 0; s < 4; ++s)
#pragma unroll
        for (int f = 0; f < 4; ++f) {
            int row = wid * 16 + (lane >> 2) + (f & 1) * 8;
            int col = s * 16 + (lane & 3) * 2 + ((f >> 1) & 1) * 8;
            float2 a = *(const float2*)(qp + (size_t)row * DH + col);
            split_pair(a.x * sc, a.y * sc, qh[s][f], ql[s][f]);
        }

    __syncthreads();
    const int kv_lo = red_lo & ~(TN - 1);
    const int kv_hi = red_hi;

    // ldmatrix per-lane base offsets
    const uint32_t base32 = smem_u32(sm);
    // K (non-trans): mat m = lane/8: row = 8*(m>>1) + lane%8 (rel), col = (m&1)*8
    const int rA = ((lane >> 4) << 3) + (lane & 7);
    const int cA = ((lane >> 3) & 1) << 3;
    const uint32_t khB = base32 + 0 * TN * KROW * 2 + 2 * (rA * KROW + cA);
    const uint32_t klB = base32 + 1 * TN * KROW * 2 + 2 * (rA * KROW + cA);
    // V (trans): mat m: row(tok rel) = (m&1)*8 + lane%8, col(d rel) = (m>>1)*8
    const int rV = (((lane >> 3) & 1) << 3) + (lane & 7);
    const int cV = ((lane >> 4) & 1) << 3;
    const uint32_t vhB = base32 + 2 * TN * KROW * 2 + 2 * (rV * KROW + cV);
    const uint32_t vlB = base32 + 3 * TN * KROW * 2 + 2 * (rV * KROW + cV);

    float oacc[8][4];
#pragma unroll
    for (int t = 0; t < 8; ++t)
#pragma unroll
        for (int c = 0; c < 4; ++c) oacc[t][c] = 0.f;
    float l0 = 0.f, l1 = 0.f;

    const int tok  = tid >> 1;           // 0..63
    const int d0   = (tid & 1) * 32;     // 0 or 32

    for (int n0 = kv_lo, iter = 0; n0 < kv_hi; n0 += TN, ++iter) {
        if (iter) __syncthreads();   // GEMM2 of prev tile done reading smem

        // ---- Load + split K, V tiles into smem bf16 hi/lo (32 floats each per thread) ----
        {
            const float* kb = kp + (size_t)(n0 + tok) * DH + d0;
            const float* vb = vp + (size_t)(n0 + tok) * DH + d0;
            const int sb = tok * KROW + d0;
#pragma unroll
            for (int j = 0; j < 8; ++j) {
                float4 a = *(const float4*)(kb + j * 4);
                uint32_t h0, h1, lo0, lo1;
                split_pair(a.x, a.y, h0, lo0);
                split_pair(a.z, a.w, h1, lo1);
                *(uint2*)&sKh[sb + j * 4] = make_uint2(h0, h1);
                *(uint2*)&sKl[sb + j * 4] = make_uint2(lo0, lo1);
            }
#pragma unroll
            for (int j = 0; j < 8; ++j) {
                float4 a = *(const float4*)(vb + j * 4);
                uint32_t h0, h1, lo0, lo1;
                split_pair(a.x, a.y, h0, lo0);
                split_pair(a.z, a.w, h1, lo1);
                *(uint2*)&sVh[sb + j * 4] = make_uint2(h0, h1);
                *(uint2*)&sVl[sb + j * 4] = make_uint2(lo0, lo1);
            }
        }
        __syncthreads();

        // ---- GEMM1: S[16x64 per warp] = Q K^T (hh + hl + lh) ----
        float sacc[8][4];
#pragma unroll
        for (int t = 0; t < 8; ++t)
#pragma unroll
            for (int c = 0; c < 4; ++c) sacc[t][c] = 0.f;

#pragma unroll
        for (int s = 0; s < 4; ++s)
#pragma unroll
            for (int p = 0; p < 4; ++p) {
                uint32_t bh4[4], bl4[4];
                const uint32_t off = (uint32_t)(p * 16 * KROW + s * 16) * 2;
                LDSM4(bh4, khB + off);
                LDSM4(bl4, klB + off);
                MMA(sacc[2 * p],     qh[s], bh4 + 0);
                MMA(sacc[2 * p + 1], qh[s], bh4 + 2);
                MMA(sacc[2 * p],     qh[s], bl4 + 0);
                MMA(sacc[2 * p + 1], qh[s], bl4 + 2);
                MMA(sacc[2 * p],     ql[s], bh4 + 0);
                MMA(sacc[2 * p + 1], ql[s], bh4 + 2);
            }

        // ---- softmax (no max-sub; scores O(1)) + build split P A-frags ----
        uint32_t pah[4][4], pal[4][4];
#pragma unroll
        for (int s = 0; s < 4; ++s) {
            const int c0a = n0 + (2 * s) * 8 + (lane & 3) * 2;
            const int c0b = c0a + 8;
            float pa0 = (c0a     >= rs0 && c0a     < re0) ? __expf(sacc[2*s][0])   : 0.f;
            float pa1 = (c0a + 1 >= rs0 && c0a + 1 < re0) ? __expf(sacc[2*s][1])   : 0.f;
            float pa2 = (c0a     >= rs1 && c0a     < re1) ? __expf(sacc[2*s][2])   : 0.f;
            float pa3 = (c0a + 1 >= rs1 && c0a + 1 < re1) ? __expf(sacc[2*s][3])   : 0.f;
            float pb0 = (c0b     >= rs0 && c0b     < re0) ? __expf(sacc[2*s+1][0]) : 0.f;
            float pb1 = (c0b + 1 >= rs0 && c0b + 1 < re0) ? __expf(sacc[2*s+1][1]) : 0.f;
            float pb2 = (c0b     >= rs1 && c0b     < re1) ? __expf(sacc[2*s+1][2]) : 0.f;
            float pb3 = (c0b + 1 >= rs1 && c0b + 1 < re1) ? __expf(sacc[2*s+1][3]) : 0.f;
            l0 += (pa0 + pa1) + (pb0 + pb1);
            l1 += (pa2 + pa3) + (pb2 + pb3);
            split_pair(pa0, pa1, pah[s][0], pal[s][0]);   // a0: rows r,   k 0-7
            split_pair(pa2, pa3, pah[s][1], pal[s][1]);   // a1: rows r+8, k 0-7
            split_pair(pb0, pb1, pah[s][2], pal[s][2]);   // a2: rows r,   k 8-15
            split_pair(pb2, pb3, pah[s][3], pal[s][3]);   // a3: rows r+8, k 8-15
        }

        // ---- GEMM2: O[16x64 per warp] += P V (hh + hl + lh) ----
#pragma unroll
        for (int s = 0; s < 4; ++s)
#pragma unroll
            for (int p = 0; p < 4; ++p) {
                uint32_t vh4[4], vl4[4];
                const uint32_t off = (uint32_t)(s * 16 * KROW + p * 16) * 2;
                LDSM4T(vh4, vhB + off);
                LDSM4T(vl4, vlB + off);
                MMA(oacc[2 * p],     pah[s], vh4 + 0);
                MMA(oacc[2 * p + 1], pah[s], vh4 + 2);
                MMA(oacc[2 * p],     pah[s], vl4 + 0);
                MMA(oacc[2 * p + 1], pah[s], vl4 + 2);
                MMA(oacc[2 * p],     pal[s], vh4 + 0);
                MMA(oacc[2 * p + 1], pal[s], vh4 + 2);
            }
    }

    // ---- epilogue: reduce l across the quad (same row), normalize, store ----
    l0 += __shfl_xor_sync(0xffffffffu, l0, 1);
    l0 += __shfl_xor_sync(0xffffffffu, l0, 2);
    l1 += __shfl_xor_sync(0xffffffffu, l1, 1);
    l1 += __shfl_xor_sync(0xffffffffu, l1, 2);
    const float inv0 = 1.0f / l0;
    const float inv1 = 1.0f / l1;

    float* orow0 = op + (size_t)rloc * DH;
#pragma unroll
    for (int t = 0; t < 8; ++t) {
        const int col = t * 8 + (lane & 3) * 2;
        *(float2*)(orow0 + col)            = make_float2(oacc[t][0] * inv0, oacc[t][1] * inv0);
        *(float2*)(orow0 + 8 * DH + col)   = make_float2(oacc[t][2] * inv1, oacc[t][3] * inv1);
    }
}

extern "C" void kernel_launch(void* const* d_in, const int* in_sizes, int n_in,
                              void* d_out, int out_size)
{
    const float* q   = (const float*)d_in[0];
    const float* k   = (const float*)d_in[1];
    const float* v   = (const float*)d_in[2];
    const float* smp = (const float*)d_in[3];
    const int* rsv   = (const int*)d_in[4];
    const int* rev   = (const int*)d_in[5];
    float* out = (float*)d_out;

    const int bh = in_sizes[0] / (NCTX * DH);   // B*H = 32
    dim3 grid(NCTX / QM, bh);
    bsattn_mma_kernel<<<grid, NTH>>>(q, k, v, smp, rsv, rev, out);
}

// round 9
// speedup vs baseline: 1.7858x; 1.7858x over previous
#include <cuda_runtime.h>
#include <cuda_bf16.h>
#include <cstdint>

#define NCTX 2048
#define DH   64
#define QM   128     // q rows per CTA
#define TN   64      // kv tokens per tile
#define NTH  256     // 8 warps
#define KROW 72      // smem row stride in bf16 elems (144B, 16B-aligned, ldmatrix conflict-free)

static __device__ __forceinline__ uint32_t smem_u32(const void* p) {
    uint32_t a;
    asm("{ .reg .u64 t; cvta.to.shared.u64 t, %1; cvt.u32.u64 %0, t; }" : "=r"(a) : "l"(p));
    return a;
}

// D += A * B, m16n8k16 bf16 -> fp32
#define MMA(d, a, b) \
    asm volatile("mma.sync.aligned.m16n8k16.row.col.f32.bf16.bf16.f32 " \
        "{%0,%1,%2,%3}, {%4,%5,%6,%7}, {%8,%9}, {%0,%1,%2,%3};" \
        : "+f"((d)[0]), "+f"((d)[1]), "+f"((d)[2]), "+f"((d)[3]) \
        : "r"((a)[0]), "r"((a)[1]), "r"((a)[2]), "r"((a)[3]), "r"((b)[0]), "r"((b)[1]))

#define LDSM4(r, addr) \
    asm volatile("ldmatrix.sync.aligned.m8n8.x4.shared.b16 {%0,%1,%2,%3}, [%4];" \
        : "=r"((r)[0]), "=r"((r)[1]), "=r"((r)[2]), "=r"((r)[3]) : "r"(addr))

#define LDSM4T(r, addr) \
    asm volatile("ldmatrix.sync.aligned.m8n8.x4.trans.shared.b16 {%0,%1,%2,%3}, [%4];" \
        : "=r"((r)[0]), "=r"((r)[1]), "=r"((r)[2]), "=r"((r)[3]) : "r"(addr))

// split (a,b) into packed bf16 hi pair + residual lo pair
static __device__ __forceinline__ void split_pair(float a, float b, uint32_t& h, uint32_t& l) {
    __nv_bfloat16 ha = __float2bfloat16(a);
    __nv_bfloat16 hb = __float2bfloat16(b);
    __nv_bfloat16 la = __float2bfloat16(a - __bfloat162float(ha));
    __nv_bfloat16 lb = __float2bfloat16(b - __bfloat162float(hb));
    h = ((uint32_t)__bfloat16_as_ushort(hb) << 16) | (uint32_t)__bfloat16_as_ushort(ha);
    l = ((uint32_t)__bfloat16_as_ushort(lb) << 16) | (uint32_t)__bfloat16_as_ushort(la);
}

__global__ __launch_bounds__(NTH, 2)
void bsattn_mma_kernel(const float* __restrict__ q, const float* __restrict__ k,
                       const float* __restrict__ v, const float* __restrict__ smp,
                       const int* __restrict__ rsv, const int* __restrict__ rev,
                       float* __restrict__ out)
{
    // Kh | Kl | Vh | Vl, each 64 tok x 72 bf16 (144B rows) = 36.9KB
    __shared__ __align__(16) uint16_t sm[4 * TN * KROW];
    __shared__ int red_lo, red_hi;

    uint16_t* sKh = sm;
    uint16_t* sKl = sm + 1 * TN * KROW;
    uint16_t* sVh = sm + 2 * TN * KROW;
    uint16_t* sVl = sm + 3 * TN * KROW;

    const int tid  = threadIdx.x;
    const int wid  = tid >> 5;
    const int lane = tid & 31;
    const int qb   = gridDim.x - 1 - blockIdx.x;   // heavy q-tiles first
    const int bh   = blockIdx.y;
    const int q0   = qb * QM;

    const float sc = *smp;
    const float* qp = q   + ((size_t)bh * NCTX + q0) * DH;
    const float* kp = k   + (size_t)bh * NCTX * DH;
    const float* vp = v   + (size_t)bh * NCTX * DH;
    float*       op = out + ((size_t)bh * NCTX + q0) * DH;

    // this thread's two query rows (within mma fragments)
    const int rloc = wid * 16 + (lane >> 2);       // row for c0/c1
    const int rg0  = q0 + rloc;
    const int rs0 = rsv[rg0],     re0 = rev[rg0];
    const int rs1 = rsv[rg0 + 8], re1 = rev[rg0 + 8];

    if (tid == 0) { red_lo = 0x7fffffff; red_hi = 0; }
    __syncthreads();
    atomicMin(&red_lo, min(rs0, rs1));
    atomicMax(&red_hi, max(re0, re1));

    // ---- Preload Q as split A-fragments (registers, reused every tile) ----
    uint32_t qh[4][4], ql[4][4];
#pragma unroll
    for (int s = 0; s < 4; ++s)
#pragma unroll
        for (int f = 0; f < 4; ++f) {
            int row = wid * 16 + (lane >> 2) + (f & 1) * 8;
            int col = s * 16 + (lane & 3) * 2 + ((f >> 1) & 1) * 8;
            float2 a = *(const float2*)(qp + (size_t)row * DH + col);
            split_pair(a.x * sc, a.y * sc, qh[s][f], ql[s][f]);
        }

    __syncthreads();
    const int kv_lo = red_lo & ~(TN - 1);
    const int kv_hi = red_hi;

    // ldmatrix per-lane base offsets
    const uint32_t base32 = smem_u32(sm);
    // K (non-trans): mat m = lane/8: row = 8*(m>>1) + lane%8 (rel), col = (m&1)*8
    const int rA = ((lane >> 4) << 3) + (lane & 7);
    const int cA = ((lane >> 3) & 1) << 3;
    const uint32_t khB = base32 + 0 * TN * KROW * 2 + 2 * (rA * KROW + cA);
    const uint32_t klB = base32 + 1 * TN * KROW * 2 + 2 * (rA * KROW + cA);
    // V (trans): mat m: row(tok rel) = (m&1)*8 + lane%8, col(d rel) = (m>>1)*8
    const int rV = (((lane >> 3) & 1) << 3) + (lane & 7);
    const int cV = ((lane >> 4) & 1) << 3;
    const uint32_t vhB = base32 + 2 * TN * KROW * 2 + 2 * (rV * KROW + cV);
    const uint32_t vlB = base32 + 3 * TN * KROW * 2 + 2 * (rV * KROW + cV);

    float oacc[8][4];
#pragma unroll
    for (int t = 0; t < 8; ++t)
#pragma unroll
        for (int c = 0; c < 4; ++c) oacc[t][c] = 0.f;
    float l0 = 0.f, l1 = 0.f;

    const int tok  = tid >> 2;           // 0..63
    const int d0   = (tid & 3) * 16;     // 0,16,32,48

    for (int n0 = kv_lo, iter = 0; n0 < kv_hi; n0 += TN, ++iter) {
        if (iter) __syncthreads();   // GEMM2 of prev tile done reading smem

        // ---- Load + split K, V tiles into smem bf16 hi/lo ----
        {
            const float* kb = kp + (size_t)(n0 + tok) * DH + d0;
            const float* vb = vp + (size_t)(n0 + tok) * DH + d0;
            const int sb = tok * KROW + d0;
#pragma unroll
            for (int j = 0; j < 4; ++j) {
                float4 a = *(const float4*)(kb + j * 4);
                uint32_t h0, h1, lo0, lo1;
                split_pair(a.x, a.y, h0, lo0);
                split_pair(a.z, a.w, h1, lo1);
                *(uint2*)&sKh[sb + j * 4] = make_uint2(h0, h1);
                *(uint2*)&sKl[sb + j * 4] = make_uint2(lo0, lo1);
            }
#pragma unroll
            for (int j = 0; j < 4; ++j) {
                float4 a = *(const float4*)(vb + j * 4);
                uint32_t h0, h1, lo0, lo1;
                split_pair(a.x, a.y, h0, lo0);
                split_pair(a.z, a.w, h1, lo1);
                *(uint2*)&sVh[sb + j * 4] = make_uint2(h0, h1);
                *(uint2*)&sVl[sb + j * 4] = make_uint2(lo0, lo1);
            }
        }
        __syncthreads();

        // ---- GEMM1: S[16x64 per warp] = Q K^T (hh + hl + lh) ----
        float sacc[8][4];
#pragma unroll
        for (int t = 0; t < 8; ++t)
#pragma unroll
            for (int c = 0; c < 4; ++c) sacc[t][c] = 0.f;

#pragma unroll
        for (int s = 0; s < 4; ++s)
#pragma unroll
            for (int p = 0; p < 4; ++p) {
                uint32_t bh4[4], bl4[4];
                const uint32_t off = (uint32_t)(p * 16 * KROW + s * 16) * 2;
                LDSM4(bh4, khB + off);
                LDSM4(bl4, klB + off);
                MMA(sacc[2 * p],     qh[s], bh4 + 0);
                MMA(sacc[2 * p + 1], qh[s], bh4 + 2);
                MMA(sacc[2 * p],     qh[s], bl4 + 0);
                MMA(sacc[2 * p + 1], qh[s], bl4 + 2);
                MMA(sacc[2 * p],     ql[s], bh4 + 0);
                MMA(sacc[2 * p + 1], ql[s], bh4 + 2);
            }

        // ---- fused softmax + GEMM2, per 16-col k-chunk s (short P live range) ----
#pragma unroll
        for (int s = 0; s < 4; ++s) {
            const int c0a = n0 + (2 * s) * 8 + (lane & 3) * 2;
            const int c0b = c0a + 8;
            float pa0 = (c0a     >= rs0 && c0a     < re0) ? __expf(sacc[2*s][0])   : 0.f;
            float pa1 = (c0a + 1 >= rs0 && c0a + 1 < re0) ? __expf(sacc[2*s][1])   : 0.f;
            float pa2 = (c0a     >= rs1 && c0a     < re1) ? __expf(sacc[2*s][2])   : 0.f;
            float pa3 = (c0a + 1 >= rs1 && c0a + 1 < re1) ? __expf(sacc[2*s][3])   : 0.f;
            float pb0 = (c0b     >= rs0 && c0b     < re0) ? __expf(sacc[2*s+1][0]) : 0.f;
            float pb1 = (c0b + 1 >= rs0 && c0b + 1 < re0) ? __expf(sacc[2*s+1][1]) : 0.f;
            float pb2 = (c0b     >= rs1 && c0b     < re1) ? __expf(sacc[2*s+1][2]) : 0.f;
            float pb3 = (c0b + 1 >= rs1 && c0b + 1 < re1) ? __expf(sacc[2*s+1][3]) : 0.f;
            l0 += (pa0 + pa1) + (pb0 + pb1);
            l1 += (pa2 + pa3) + (pb2 + pb3);

            uint32_t pah[4], pal[4];
            split_pair(pa0, pa1, pah[0], pal[0]);   // rows r,   k 0-7
            split_pair(pa2, pa3, pah[1], pal[1]);   // rows r+8, k 0-7
            split_pair(pb0, pb1, pah[2], pal[2]);   // rows r,   k 8-15
            split_pair(pb2, pb3, pah[3], pal[3]);   // rows r+8, k 8-15

#pragma unroll
            for (int p = 0; p < 4; ++p) {
                uint32_t vh4[4], vl4[4];
                const uint32_t off = (uint32_t)(s * 16 * KROW + p * 16) * 2;
                LDSM4T(vh4, vhB + off);
                LDSM4T(vl4, vlB + off);
                MMA(oacc[2 * p],     pah, vh4 + 0);
                MMA(oacc[2 * p + 1], pah, vh4 + 2);
                MMA(oacc[2 * p],     pah, vl4 + 0);
                MMA(oacc[2 * p + 1], pah, vl4 + 2);
                MMA(oacc[2 * p],     pal, vh4 + 0);
                MMA(oacc[2 * p + 1], pal, vh4 + 2);
            }
        }
    }

    // ---- epilogue: reduce l across the quad (same row), normalize, store ----
    l0 += __shfl_xor_sync(0xffffffffu, l0, 1);
    l0 += __shfl_xor_sync(0xffffffffu, l0, 2);
    l1 += __shfl_xor_sync(0xffffffffu, l1, 1);
    l1 += __shfl_xor_sync(0xffffffffu, l1, 2);
    const float inv0 = 1.0f / l0;
    const float inv1 = 1.0f / l1;

    float* orow0 = op + (size_t)rloc * DH;
#pragma unroll
    for (int t = 0; t < 8; ++t) {
        const int col = t * 8 + (lane & 3) * 2;
        *(float2*)(orow0 + col)            = make_float2(oacc[t][0] * inv0, oacc[t][1] * inv0);
        *(float2*)(orow0 + 8 * DH + col)   = make_float2(oacc[t][2] * inv1, oacc[t][3] * inv1);
    }
}

extern "C" void kernel_launch(void* const* d_in, const int* in_sizes, int n_in,
                              void* d_out, int out_size)
{
    const float* q   = (const float*)d_in[0];
    const float* k   = (const float*)d_in[1];
    const float* v   = (const float*)d_in[2];
    const float* smp = (const float*)d_in[3];
    const int* rsv   = (const int*)d_in[4];
    const int* rev   = (const int*)d_in[5];
    float* out = (float*)d_out;

    const int bh = in_sizes[0] / (NCTX * DH);   // B*H = 32
    dim3 grid(NCTX / QM, bh);
    bsattn_mma_kernel<<<grid, NTH>>>(q, k, v, smp, rsv, rev, out);
}